// round 8
// baseline (speedup 1.0000x reference)
#include <cuda_runtime.h>
#include <stdint.h>

// UniformShardedEmbeddingBags: weights [E,T,D] fp32, indices [B,T,L] int32 -> out [B,T,D] fp32
// E=200000, T=16, D=64, B=4096, L=20
#define EB_E 200000
#define EB_T 16
#define EB_D 64
#define EB_L 20
#define EB_B 4096

// One warp per bag. MLP is decoupled from the register file using cp.async
// (LDGSTS): all 20 row gathers are issued as 16B cp.async.cg (L1-bypass ->
// shared) with NO destination registers pinned, so the full window is
// guaranteed in flight (ptxas collapsed every register-based attempt to 32
// regs / shallow batches in R3-R7).
//
// Per iteration, the warp's 32 lanes move TWO rows (16 lanes x float4 each):
// 10 LDGSTS per lane, each 16B, perfectly coalesced 2x128B per row.
// Shared: 8 warps x 20 rows x 256B = 40KB/block -> 5 blocks/SM = 40 warps,
// ~200KB of gather bytes outstanding per SM (~2.5x the R7 config) to fill
// DRAM channel queues through their imbalance.
//
// Grid stays TABLE-MAJOR so L2 keeps capturing the ~1.22x per-table row reuse.
__global__ __launch_bounds__(256) void embbag_kernel(
    const float* __restrict__ weights,
    const int* __restrict__ indices,
    float* __restrict__ out)
{
    __shared__ float4 sbuf[8][EB_L][16];   // 40960 bytes

    const int warp = threadIdx.x >> 5;                  // 0..7
    const int lane = threadIdx.x & 31;

    const int t = blockIdx.x >> 9;                      // table 0..15 (512 blocks each)
    const int b = ((blockIdx.x & 511) << 3) + warp;     // batch 0..4095
    const int bag = b * EB_T + t;

    // Lanes 0..19 fetch this bag's indices; one coalesced transaction.
    int myidx = 0;
    if (lane < EB_L) myidx = __ldg(indices + (size_t)bag * EB_L + lane);

    const int slot = lane & 15;   // float4 slot within the 256B row
    const int half = lane >> 4;   // which row of the pair this lane serves

    uint32_t dst_base = (uint32_t)__cvta_generic_to_shared(&sbuf[warp][0][0]);

    // Phase 1: issue ALL 20 row gathers via cp.async (2 rows per iteration).
#pragma unroll
    for (int l = 0; l < EB_L; l += 2) {
        int row = l + half;
        int e = __shfl_sync(0xFFFFFFFFu, myidx, row);
        const float4* src = reinterpret_cast<const float4*>(
            weights + ((size_t)e * EB_T + t) * EB_D) + slot;
        uint32_t dst = dst_base + (uint32_t)(row * 16 + slot) * 16u;
        asm volatile("cp.async.cg.shared.global [%0], [%1], 16;\n"
                     :: "r"(dst), "l"(src));
    }
    asm volatile("cp.async.commit_group;\n");
    asm volatile("cp.async.wait_group 0;\n" ::: "memory");
    __syncwarp();

    // Phase 2: reduce from shared. Lane owns one float2 slot: 32 lanes x 8B
    // spans the full 256B row -> conflict-free LDS.64 in 2 phases.
    const float2* s2 = reinterpret_cast<const float2*>(&sbuf[warp][0][0]);
    float accx = 0.f, accy = 0.f;
#pragma unroll
    for (int l = 0; l < EB_L; ++l) {
        float2 v = s2[l * 32 + lane];
        accx += v.x;
        accy += v.y;
    }

    reinterpret_cast<float2*>(out)[(size_t)bag * 32 + lane] = make_float2(accx, accy);
}

extern "C" void kernel_launch(void* const* d_in, const int* in_sizes, int n_in,
                              void* d_out, int out_size)
{
    // weights = 204,800,000 elems ; indices = 1,310,720 elems
    const float* weights = (const float*)d_in[0];
    const int*   indices = (const int*)d_in[1];
    if (n_in >= 2 && in_sizes[0] < in_sizes[1]) {
        weights = (const float*)d_in[1];
        indices = (const int*)d_in[0];
    }
    float* out = (float*)d_out;

    const int block = 256;                 // 8 warps = 8 bags per block
    const int grid = EB_T * 512;           // 8192 blocks, table-major
    embbag_kernel<<<grid, block>>>(weights, indices, out);
}

// round 9
// speedup vs baseline: 1.0385x; 1.0385x over previous
#include <cuda_runtime.h>
#include <stdint.h>

// UniformShardedEmbeddingBags: weights [E,T,D] fp32, indices [B,T,L] int32 -> out [B,T,D] fp32
// E=200000, T=16, D=64, B=4096, L=20
#define EB_E 200000
#define EB_T 16
#define EB_D 64
#define EB_L 20
#define EB_B 4096

// One warp per bag; all 20 row gathers issued as 16B cp.async.cg (L1-bypass ->
// shared), guaranteeing the full 20-deep window regardless of register
// allocation. This round: 128-thread blocks (4 warps, 20.5KB smem) so 11
// blocks (44 warps) fit per SM -> ~880 guaranteed in-flight row gathers
// (~225KB) per SM at 69% occupancy, vs R8's 40 warps at 46%. More warps also
// overlap the idx-load / TMA-wait / reduce phases across bags.
//
// Per iteration the warp's 32 lanes move TWO rows (16 lanes x 16B each):
// 10 LDGSTS per lane, perfectly coalesced 2x128B per row.
//
// Grid stays TABLE-MAJOR so L2 keeps capturing the ~1.22x per-table row reuse
// (DRAM bytes are already at the dedup floor; we are chasing DRAM-active%).
__global__ __launch_bounds__(128, 11) void embbag_kernel(
    const float* __restrict__ weights,
    const int* __restrict__ indices,
    float* __restrict__ out)
{
    __shared__ float4 sbuf[4][EB_L][16];   // 20480 bytes

    const int warp = threadIdx.x >> 5;                  // 0..3
    const int lane = threadIdx.x & 31;

    const int t = blockIdx.x >> 10;                     // table 0..15 (1024 blocks each)
    const int b = ((blockIdx.x & 1023) << 2) + warp;    // batch 0..4095
    const int bag = b * EB_T + t;

    // Lanes 0..19 fetch this bag's indices; one coalesced transaction.
    int myidx = 0;
    if (lane < EB_L) myidx = __ldg(indices + (size_t)bag * EB_L + lane);

    const int slot = lane & 15;   // float4 slot within the 256B row
    const int half = lane >> 4;   // which row of the pair this lane serves

    uint32_t dst_base = (uint32_t)__cvta_generic_to_shared(&sbuf[warp][0][0]);

    // Phase 1: issue ALL 20 row gathers via cp.async (2 rows per iteration).
#pragma unroll
    for (int l = 0; l < EB_L; l += 2) {
        int row = l + half;
        int e = __shfl_sync(0xFFFFFFFFu, myidx, row);
        const float4* src = reinterpret_cast<const float4*>(
            weights + ((size_t)e * EB_T + t) * EB_D) + slot;
        uint32_t dst = dst_base + (uint32_t)(row * 16 + slot) * 16u;
        asm volatile("cp.async.cg.shared.global [%0], [%1], 16;\n"
                     :: "r"(dst), "l"(src));
    }
    asm volatile("cp.async.commit_group;\n");
    asm volatile("cp.async.wait_group 0;\n" ::: "memory");
    __syncwarp();

    // Phase 2: reduce from shared. Lane owns one float2 slot: 32 lanes x 8B
    // spans the full 256B row -> conflict-free LDS.64.
    const float2* s2 = reinterpret_cast<const float2*>(&sbuf[warp][0][0]);
    float accx = 0.f, accy = 0.f;
#pragma unroll
    for (int l = 0; l < EB_L; ++l) {
        float2 v = s2[l * 32 + lane];
        accx += v.x;
        accy += v.y;
    }

    // Streaming store: output is write-once, keep it out of L2's gather set.
    float2 r = make_float2(accx, accy);
    float2* dst = reinterpret_cast<float2*>(out) + (size_t)bag * 32 + lane;
    asm volatile("st.global.cs.v2.f32 [%0], {%1, %2};\n"
                 :: "l"(dst), "f"(r.x), "f"(r.y));
}

extern "C" void kernel_launch(void* const* d_in, const int* in_sizes, int n_in,
                              void* d_out, int out_size)
{
    // weights = 204,800,000 elems ; indices = 1,310,720 elems
    const float* weights = (const float*)d_in[0];
    const int*   indices = (const int*)d_in[1];
    if (n_in >= 2 && in_sizes[0] < in_sizes[1]) {
        weights = (const float*)d_in[1];
        indices = (const int*)d_in[0];
    }
    float* out = (float*)d_out;

    const int block = 128;                 // 4 warps = 4 bags per block
    const int grid = EB_T * 1024;          // 16384 blocks, table-major
    embbag_kernel<<<grid, block>>>(weights, indices, out);
}